// round 8
// baseline (speedup 1.0000x reference)
#include <cuda_runtime.h>
#include <cstdint>

#define NN 50000      // nodes
#define NE 1250000    // edges
#define DN 64         // node feat
#define DE 16         // edge feat
#define DH 64         // hidden

// ---------------------------------------------------------------------------
// Scratch (device globals; no allocation allowed)
// ---------------------------------------------------------------------------
__device__ float g_srcpart[NN * DH];   // node_features @ W_m1[0:64]
__device__ float g_xu[NN * DH];        // node_features @ W_u1[0:64]
__device__ float g_hsum[NN * DH];      // per-node aggregated messages
__device__ int   g_deg[NN];            // in-degree per node
__device__ int   g_start[NN];          // CSR row start (exclusive scan of deg)
__device__ int   g_cursor[NN];         // scatter cursors
__device__ int   g_bsum[256];          // scan block sums
__device__ int   g_boff[256];          // scanned block offsets
__device__ int2  g_sorted[NE];         // (src, edge_id) sorted by dst
__device__ float g_Wc[DH * DH];        // W_m2 @ W_u1[64:128]
__device__ float g_bc[DH];             // b_m2 @ W_u1[64:128]

#define NB196 196   // ceil(NN/256)

// ---------------------------------------------------------------------------
// initA: blocks [0,196) zero g_deg; blocks 196+k (k<64): Wc row k; block 260: bc
// ---------------------------------------------------------------------------
__global__ void initA_kernel(const float* __restrict__ w_m2,
                             const float* __restrict__ b_m2,
                             const float* __restrict__ w_u1) {
    const int tid = threadIdx.x;
    if (blockIdx.x < NB196) {
        int idx = blockIdx.x * 256 + tid;
        if (idx < NN) g_deg[idx] = 0;
    } else if (blockIdx.x < NB196 + 64) {
        int k = blockIdx.x - NB196;
        if (tid < DH) {
            float s = 0.f;
            #pragma unroll 8
            for (int m = 0; m < DH; m++)
                s += w_m2[k * DH + m] * w_u1[(DN + m) * DH + tid];
            g_Wc[k * DH + tid] = s;
        }
    } else {
        if (tid < DH) {
            float s = 0.f;
            #pragma unroll 8
            for (int m = 0; m < DH; m++)
                s += b_m2[m] * w_u1[(DN + m) * DH + tid];
            g_bc[tid] = s;
        }
    }
}

// ---------------------------------------------------------------------------
// pre_gemm + degree histogram in one launch.
//   blocks [0,391): stage X tile once -> g_srcpart = X@Wm1a, g_xu = X@Wu1a
//   blocks [391, 391+4883): deg histogram (coalesced dst reads, int atomics)
// ---------------------------------------------------------------------------
#define PGB 391    // ceil(NN/128)
#define DGB 4883   // ceil(NE/256)
__global__ void pre_gemm_kernel(const float* __restrict__ X,
                                const float* __restrict__ w_m1,
                                const float* __restrict__ w_u1,
                                const int* __restrict__ eidx) {
    const int tid = threadIdx.x;
    if (blockIdx.x >= PGB) {
        int e = (blockIdx.x - PGB) * 256 + tid;
        if (e < NE) atomicAdd(&g_deg[eidx[NE + e]], 1);
        return;
    }
    __shared__ float As[128 * 66];
    const int row0 = blockIdx.x * 128;

    for (int idx = tid; idx < 128 * 64; idx += 256) {
        int r = idx >> 6, k = idx & 63;
        int row = row0 + r;
        As[r * 66 + k] = (row < NN) ? X[(size_t)row * 64 + k] : 0.f;
    }
    __syncthreads();

    const int tc = tid & 15, tr = tid >> 4;
    const int j0 = tc * 4, r0 = tr * 8;
    float4 acc[8];

    #pragma unroll
    for (int i = 0; i < 8; i++) acc[i] = make_float4(0.f, 0.f, 0.f, 0.f);
    #pragma unroll 8
    for (int k = 0; k < 64; k++) {
        float4 w = *reinterpret_cast<const float4*>(&w_m1[k * 64 + j0]);
        #pragma unroll
        for (int i = 0; i < 8; i++) {
            float a = As[(r0 + i) * 66 + k];
            acc[i].x += a * w.x; acc[i].y += a * w.y;
            acc[i].z += a * w.z; acc[i].w += a * w.w;
        }
    }
    #pragma unroll
    for (int i = 0; i < 8; i++) {
        int row = row0 + r0 + i;
        if (row < NN)
            *reinterpret_cast<float4*>(&g_srcpart[(size_t)row * 64 + j0]) = acc[i];
    }

    #pragma unroll
    for (int i = 0; i < 8; i++) acc[i] = make_float4(0.f, 0.f, 0.f, 0.f);
    #pragma unroll 8
    for (int k = 0; k < 64; k++) {
        float4 w = *reinterpret_cast<const float4*>(&w_u1[k * 64 + j0]);
        #pragma unroll
        for (int i = 0; i < 8; i++) {
            float a = As[(r0 + i) * 66 + k];
            acc[i].x += a * w.x; acc[i].y += a * w.y;
            acc[i].z += a * w.z; acc[i].w += a * w.w;
        }
    }
    #pragma unroll
    for (int i = 0; i < 8; i++) {
        int row = row0 + r0 + i;
        if (row < NN)
            *reinterpret_cast<float4*>(&g_xu[(size_t)row * 64 + j0]) = acc[i];
    }
}

// ---------------------------------------------------------------------------
// 3-kernel exclusive scan over g_deg -> g_start (+ g_cursor copy).
// ---------------------------------------------------------------------------
__global__ void scan1_kernel() {
    __shared__ int sh[256];
    const int tid = threadIdx.x;
    int i = blockIdx.x * 256 + tid;
    int v = (i < NN) ? g_deg[i] : 0;
    sh[tid] = v;
    __syncthreads();
    #pragma unroll
    for (int off = 1; off < 256; off <<= 1) {
        int t = (tid >= off) ? sh[tid - off] : 0;
        __syncthreads();
        sh[tid] += t;
        __syncthreads();
    }
    if (i < NN) g_start[i] = sh[tid] - v;        // exclusive within block
    if (tid == 255) g_bsum[blockIdx.x] = sh[255];
}

__global__ void scan2_kernel() {
    __shared__ int sh[256];
    const int tid = threadIdx.x;
    int v = (tid < NB196) ? g_bsum[tid] : 0;
    sh[tid] = v;
    __syncthreads();
    #pragma unroll
    for (int off = 1; off < 256; off <<= 1) {
        int t = (tid >= off) ? sh[tid - off] : 0;
        __syncthreads();
        sh[tid] += t;
        __syncthreads();
    }
    g_boff[tid] = sh[tid] - v;                   // exclusive block offsets
}

__global__ void scan3_kernel() {
    int i = blockIdx.x * 256 + threadIdx.x;
    if (i < NN) {
        int s = g_start[i] + g_boff[blockIdx.x];
        g_start[i] = s;
        g_cursor[i] = s;
    }
}

// ---------------------------------------------------------------------------
// scatter: counting-sort edges by dst -> g_sorted[(src, edge_id)]
// ---------------------------------------------------------------------------
__global__ void scatter_kernel(const int* __restrict__ eidx) {
    int e = blockIdx.x * 256 + threadIdx.x;
    if (e < NE) {
        int s = eidx[e];
        int d = eidx[NE + e];
        int pos = atomicAdd(&g_cursor[d], 1);
        g_sorted[pos] = make_int2(s, e);
    }
}

// ---------------------------------------------------------------------------
// agg: one warp per dst node, ZERO atomics.  Lane owns cols (lane, lane+32);
// edge-GEMM weights live in 32 registers per lane.  Per edge:
//   h = relu(srcpart[src] + ef[e]@Wm1b + b_m1);  acc += h.
// ---------------------------------------------------------------------------
__global__ void __launch_bounds__(256, 4)
agg_kernel(const float* __restrict__ ef,
           const float* __restrict__ w_m1,
           const float* __restrict__ b_m1) {
    const int tid = threadIdx.x;
    const int lane = tid & 31, wrp = tid >> 5;
    const int n = blockIdx.x * 8 + wrp;
    if (n >= NN) return;

    float Wr0[16], Wr1[16];
    #pragma unroll
    for (int k = 0; k < 16; k++) {
        Wr0[k] = w_m1[(DN + k) * 64 + lane];
        Wr1[k] = w_m1[(DN + k) * 64 + lane + 32];
    }
    const float b0 = b_m1[lane];
    const float b1 = b_m1[lane + 32];

    const int start = g_start[n];
    const int deg = g_deg[n];
    float acc0 = 0.f, acc1 = 0.f;

    #pragma unroll 2
    for (int i = 0; i < deg; i++) {
        int2 es = g_sorted[start + i];
        const float* sp = g_srcpart + (size_t)es.x * 64;
        float a0 = sp[lane];
        float a1 = sp[lane + 32];
        const float4* efp = reinterpret_cast<const float4*>(ef + (size_t)es.y * 16);
        float4 v0 = efp[0], v1 = efp[1], v2 = efp[2], v3 = efp[3];

        float h0 = a0 + b0, h1 = a1 + b1;
        h0 = fmaf(v0.x, Wr0[0], h0);  h1 = fmaf(v0.x, Wr1[0], h1);
        h0 = fmaf(v0.y, Wr0[1], h0);  h1 = fmaf(v0.y, Wr1[1], h1);
        h0 = fmaf(v0.z, Wr0[2], h0);  h1 = fmaf(v0.z, Wr1[2], h1);
        h0 = fmaf(v0.w, Wr0[3], h0);  h1 = fmaf(v0.w, Wr1[3], h1);
        h0 = fmaf(v1.x, Wr0[4], h0);  h1 = fmaf(v1.x, Wr1[4], h1);
        h0 = fmaf(v1.y, Wr0[5], h0);  h1 = fmaf(v1.y, Wr1[5], h1);
        h0 = fmaf(v1.z, Wr0[6], h0);  h1 = fmaf(v1.z, Wr1[6], h1);
        h0 = fmaf(v1.w, Wr0[7], h0);  h1 = fmaf(v1.w, Wr1[7], h1);
        h0 = fmaf(v2.x, Wr0[8], h0);  h1 = fmaf(v2.x, Wr1[8], h1);
        h0 = fmaf(v2.y, Wr0[9], h0);  h1 = fmaf(v2.y, Wr1[9], h1);
        h0 = fmaf(v2.z, Wr0[10], h0); h1 = fmaf(v2.z, Wr1[10], h1);
        h0 = fmaf(v2.w, Wr0[11], h0); h1 = fmaf(v2.w, Wr1[11], h1);
        h0 = fmaf(v3.x, Wr0[12], h0); h1 = fmaf(v3.x, Wr1[12], h1);
        h0 = fmaf(v3.y, Wr0[13], h0); h1 = fmaf(v3.y, Wr1[13], h1);
        h0 = fmaf(v3.z, Wr0[14], h0); h1 = fmaf(v3.z, Wr1[14], h1);
        h0 = fmaf(v3.w, Wr0[15], h0); h1 = fmaf(v3.w, Wr1[15], h1);

        acc0 += fmaxf(h0, 0.f);
        acc1 += fmaxf(h1, 0.f);
    }

    g_hsum[(size_t)n * 64 + lane] = acc0;
    g_hsum[(size_t)n * 64 + lane + 32] = acc1;
}

// ---------------------------------------------------------------------------
// Fused node update: 128-row tiles, 8 rows x 4 cols/thread, two passes:
//   T = relu(Hsum@Wc + xu + deg*bc + b_u1);  out = T @ w_u2 + b_u2
// ---------------------------------------------------------------------------
__global__ void fused_node_kernel(const float* __restrict__ w_u2,
                                  const float* __restrict__ b_u1,
                                  const float* __restrict__ b_u2,
                                  float* __restrict__ out) {
    __shared__ float As[128 * 66];
    const int row0 = blockIdx.x * 128;
    const int tid = threadIdx.x;
    const int tc = tid & 15, tr = tid >> 4;
    const int j0 = tc * 4, r0 = tr * 8;

    for (int idx = tid; idx < 128 * 64; idx += 256) {
        int r = idx >> 6, k = idx & 63;
        int row = row0 + r;
        As[r * 66 + k] = (row < NN) ? g_hsum[(size_t)row * 64 + k] : 0.f;
    }
    __syncthreads();

    float4 acc[8];
    #pragma unroll
    for (int i = 0; i < 8; i++) acc[i] = make_float4(0.f, 0.f, 0.f, 0.f);
    #pragma unroll 8
    for (int k = 0; k < 64; k++) {
        float4 w = *reinterpret_cast<const float4*>(&g_Wc[k * 64 + j0]);
        #pragma unroll
        for (int i = 0; i < 8; i++) {
            float a = As[(r0 + i) * 66 + k];
            acc[i].x += a * w.x; acc[i].y += a * w.y;
            acc[i].z += a * w.z; acc[i].w += a * w.w;
        }
    }
    __syncthreads();

    {
        float4 bc = *reinterpret_cast<const float4*>(&g_bc[j0]);
        float4 bu = *reinterpret_cast<const float4*>(&b_u1[j0]);
        #pragma unroll
        for (int i = 0; i < 8; i++) {
            int r = r0 + i;
            int row = row0 + r;
            if (row < NN) {
                float4 xu = *reinterpret_cast<const float4*>(
                    &g_xu[(size_t)row * 64 + j0]);
                float dg = (float)g_deg[row];
                As[r * 66 + j0 + 0] = fmaxf(acc[i].x + xu.x + dg * bc.x + bu.x, 0.f);
                As[r * 66 + j0 + 1] = fmaxf(acc[i].y + xu.y + dg * bc.y + bu.y, 0.f);
                As[r * 66 + j0 + 2] = fmaxf(acc[i].z + xu.z + dg * bc.z + bu.z, 0.f);
                As[r * 66 + j0 + 3] = fmaxf(acc[i].w + xu.w + dg * bc.w + bu.w, 0.f);
            } else {
                As[r * 66 + j0 + 0] = 0.f;
                As[r * 66 + j0 + 1] = 0.f;
                As[r * 66 + j0 + 2] = 0.f;
                As[r * 66 + j0 + 3] = 0.f;
            }
        }
    }
    __syncthreads();

    #pragma unroll
    for (int i = 0; i < 8; i++) acc[i] = make_float4(0.f, 0.f, 0.f, 0.f);
    #pragma unroll 8
    for (int k = 0; k < 64; k++) {
        float4 w = *reinterpret_cast<const float4*>(&w_u2[k * 64 + j0]);
        #pragma unroll
        for (int i = 0; i < 8; i++) {
            float a = As[(r0 + i) * 66 + k];
            acc[i].x += a * w.x; acc[i].y += a * w.y;
            acc[i].z += a * w.z; acc[i].w += a * w.w;
        }
    }

    float4 b2 = *reinterpret_cast<const float4*>(&b_u2[j0]);
    #pragma unroll
    for (int i = 0; i < 8; i++) {
        int row = row0 + r0 + i;
        if (row < NN) {
            float4 v;
            v.x = acc[i].x + b2.x; v.y = acc[i].y + b2.y;
            v.z = acc[i].z + b2.z; v.w = acc[i].w + b2.w;
            *reinterpret_cast<float4*>(&out[(size_t)row * 64 + j0]) = v;
        }
    }
}

// ---------------------------------------------------------------------------
// Launch
// ---------------------------------------------------------------------------
extern "C" void kernel_launch(void* const* d_in, const int* in_sizes, int n_in,
                              void* d_out, int out_size) {
    const float* node_f = (const float*)d_in[0];
    const float* edge_f = (const float*)d_in[1];
    const int*   eidx   = (const int*)d_in[2];
    const float* w_m1   = (const float*)d_in[3];
    const float* b_m1   = (const float*)d_in[4];
    const float* w_m2   = (const float*)d_in[5];
    const float* b_m2   = (const float*)d_in[6];
    const float* w_u1   = (const float*)d_in[7];
    const float* b_u1   = (const float*)d_in[8];
    const float* w_u2   = (const float*)d_in[9];
    const float* b_u2   = (const float*)d_in[10];
    float* out = (float*)d_out;

    initA_kernel<<<NB196 + 65, 256>>>(w_m2, b_m2, w_u1);
    pre_gemm_kernel<<<PGB + DGB, 256>>>(node_f, w_m1, w_u1, eidx);
    scan1_kernel<<<NB196, 256>>>();
    scan2_kernel<<<1, 256>>>();
    scan3_kernel<<<NB196, 256>>>();
    scatter_kernel<<<DGB, 256>>>(eidx);
    agg_kernel<<<(NN + 7) / 8, 256>>>(edge_f, w_m1, b_m1);
    fused_node_kernel<<<PGB, 256>>>(w_u2, b_u1, b_u2, out);
}

// round 9
// speedup vs baseline: 1.0701x; 1.0701x over previous
#include <cuda_runtime.h>
#include <cstdint>

#define NN 50000      // nodes
#define NE 1250000    // edges
#define DN 64         // node feat
#define DE 16         // edge feat
#define DH 64         // hidden

// ---------------------------------------------------------------------------
// Scratch (device globals; no allocation allowed)
// ---------------------------------------------------------------------------
__device__ float g_srcpart[NN * DH];   // node_features @ W_m1[0:64]
__device__ float g_xu[NN * DH];        // node_features @ W_u1[0:64]
__device__ float g_hsum[NN * DH];      // segment-sum of relu hidden
__device__ int   g_deg[NN];            // in-degree per node
__device__ float g_Wc[DH * DH];        // W_m2 @ W_u1[64:128]
__device__ float g_bc[DH];             // b_m2 @ W_u1[64:128]

// ---------------------------------------------------------------------------
// mega_pre: ONE launch, grid-partitioned independent work:
//   blocks [0, PGB)            : stage X tile once -> g_srcpart = X@Wm1a,
//                                g_xu = X@Wu1a   (128-row tiles, 8x4/thread)
//   blocks [PGB, PGB+ZB)       : zero g_hsum + g_deg
//   blocks PGB+ZB+k (k<64)     : Wc row k (coalesced over tid)
//   block  PGB+ZB+64           : bc
// ---------------------------------------------------------------------------
#define PGB 391    // ceil(NN/128)
#define ZB 3125    // NN*DH/4 / 256
__global__ void mega_pre_kernel(const float* __restrict__ X,
                                const float* __restrict__ w_m1,
                                const float* __restrict__ w_u1,
                                const float* __restrict__ w_m2,
                                const float* __restrict__ b_m2) {
    const int tid = threadIdx.x;

    if (blockIdx.x >= PGB) {
        int bz = blockIdx.x - PGB;
        if (bz < ZB) {
            int idx = bz * 256 + tid;
            reinterpret_cast<float4*>(g_hsum)[idx] = make_float4(0.f, 0.f, 0.f, 0.f);
            if (idx < NN) g_deg[idx] = 0;
        } else if (bz < ZB + 64) {
            int k = bz - ZB;
            if (tid < DH) {
                float s = 0.f;
                #pragma unroll 8
                for (int m = 0; m < DH; m++)
                    s += w_m2[k * DH + m] * w_u1[(DN + m) * DH + tid];
                g_Wc[k * DH + tid] = s;
            }
        } else {
            if (tid < DH) {
                float s = 0.f;
                #pragma unroll 8
                for (int m = 0; m < DH; m++)
                    s += b_m2[m] * w_u1[(DN + m) * DH + tid];
                g_bc[tid] = s;
            }
        }
        return;
    }

    __shared__ float As[128 * 66];
    const int row0 = blockIdx.x * 128;

    for (int idx = tid; idx < 128 * 64; idx += 256) {
        int r = idx >> 6, k = idx & 63;
        int row = row0 + r;
        As[r * 66 + k] = (row < NN) ? X[(size_t)row * 64 + k] : 0.f;
    }
    __syncthreads();

    const int tc = tid & 15, tr = tid >> 4;
    const int j0 = tc * 4, r0 = tr * 8;
    float4 acc[8];

    // --- srcpart = X @ w_m1[0:64] ---
    #pragma unroll
    for (int i = 0; i < 8; i++) acc[i] = make_float4(0.f, 0.f, 0.f, 0.f);
    #pragma unroll 8
    for (int k = 0; k < 64; k++) {
        float4 w = *reinterpret_cast<const float4*>(&w_m1[k * 64 + j0]);
        #pragma unroll
        for (int i = 0; i < 8; i++) {
            float a = As[(r0 + i) * 66 + k];
            acc[i].x += a * w.x; acc[i].y += a * w.y;
            acc[i].z += a * w.z; acc[i].w += a * w.w;
        }
    }
    #pragma unroll
    for (int i = 0; i < 8; i++) {
        int row = row0 + r0 + i;
        if (row < NN)
            *reinterpret_cast<float4*>(&g_srcpart[(size_t)row * 64 + j0]) = acc[i];
    }

    // --- xu = X @ w_u1[0:64] ---
    #pragma unroll
    for (int i = 0; i < 8; i++) acc[i] = make_float4(0.f, 0.f, 0.f, 0.f);
    #pragma unroll 8
    for (int k = 0; k < 64; k++) {
        float4 w = *reinterpret_cast<const float4*>(&w_u1[k * 64 + j0]);
        #pragma unroll
        for (int i = 0; i < 8; i++) {
            float a = As[(r0 + i) * 66 + k];
            acc[i].x += a * w.x; acc[i].y += a * w.y;
            acc[i].z += a * w.z; acc[i].w += a * w.w;
        }
    }
    #pragma unroll
    for (int i = 0; i < 8; i++) {
        int row = row0 + r0 + i;
        if (row < NN)
            *reinterpret_cast<float4*>(&g_xu[(size_t)row * 64 + j0]) = acc[i];
    }
}

// ---------------------------------------------------------------------------
// Edge kernel (best measured config, unchanged): 64 edges / 256-thread block,
// 4 edges x 4 cols per thread, 4 blocks/SM.  Inline deg histogram.
// ---------------------------------------------------------------------------
__global__ void __launch_bounds__(256, 4)
edge_kernel(const float* __restrict__ ef,
            const int* __restrict__ eidx,
            const float* __restrict__ w_m1,
            const float* __restrict__ b_m1) {
    __shared__ float Es[64 * 17];
    __shared__ int s_sh[64];
    __shared__ int d_sh[64];
    const int e0 = blockIdx.x * 64;
    const int tid = threadIdx.x;

    if (tid < 64) {
        int e = e0 + tid;
        int s = 0, d = 0;
        if (e < NE) {
            s = eidx[e];
            d = eidx[NE + e];
            atomicAdd(&g_deg[d], 1);
        }
        s_sh[tid] = s;
        d_sh[tid] = d;
    }
    {
        int r = tid >> 2, q = tid & 3;   // 64 edges x 4 float4 = 256 loads
        int e = e0 + r;
        float4 v = make_float4(0.f, 0.f, 0.f, 0.f);
        if (e < NE)
            v = reinterpret_cast<const float4*>(ef)[(size_t)e * 4 + q];
        Es[r * 17 + q * 4 + 0] = v.x;
        Es[r * 17 + q * 4 + 1] = v.y;
        Es[r * 17 + q * 4 + 2] = v.z;
        Es[r * 17 + q * 4 + 3] = v.w;
    }
    __syncthreads();

    const int tc = tid & 15, tr = tid >> 4;
    const int j0 = tc * 4, r0 = tr * 4;

    // Prefetch the 4 srcpart gathers early (independent L2 hits, MLP=4).
    float4 sp[4];
    #pragma unroll
    for (int i = 0; i < 4; i++) {
        int e = e0 + r0 + i;
        const float* p = &g_srcpart[(size_t)s_sh[r0 + i] * 64 + j0];
        sp[i] = (e < NE) ? *reinterpret_cast<const float4*>(p)
                         : make_float4(0.f, 0.f, 0.f, 0.f);
    }

    float4 acc[4];
    #pragma unroll
    for (int i = 0; i < 4; i++) acc[i] = make_float4(0.f, 0.f, 0.f, 0.f);

    #pragma unroll
    for (int k = 0; k < 16; k++) {
        float4 w = *reinterpret_cast<const float4*>(&w_m1[(DN + k) * 64 + j0]);
        #pragma unroll
        for (int i = 0; i < 4; i++) {
            float a = Es[(r0 + i) * 17 + k];
            acc[i].x += a * w.x; acc[i].y += a * w.y;
            acc[i].z += a * w.z; acc[i].w += a * w.w;
        }
    }

    float4 b = *reinterpret_cast<const float4*>(&b_m1[j0]);

    #pragma unroll
    for (int i = 0; i < 4; i++) {
        int e = e0 + r0 + i;
        if (e < NE) {
            float hx = fmaxf(acc[i].x + sp[i].x + b.x, 0.f);
            float hy = fmaxf(acc[i].y + sp[i].y + b.y, 0.f);
            float hz = fmaxf(acc[i].z + sp[i].z + b.z, 0.f);
            float hw = fmaxf(acc[i].w + sp[i].w + b.w, 0.f);
            float* p = &g_hsum[(size_t)d_sh[r0 + i] * 64 + j0];
            asm volatile("red.global.add.v4.f32 [%0], {%1, %2, %3, %4};"
                         :: "l"(p), "f"(hx), "f"(hy), "f"(hz), "f"(hw)
                         : "memory");
        }
    }
}

// ---------------------------------------------------------------------------
// Fused node update: 128-row tiles, 8 rows x 4 cols/thread, two passes:
//   T = relu(Hsum@Wc + xu + deg*bc + b_u1);  out = T @ w_u2 + b_u2
// launch_bounds(256,4): cap regs at 64 for 4 blocks/SM (inner loop fits;
// any spill lands in the epilogue only).
// ---------------------------------------------------------------------------
__global__ void __launch_bounds__(256, 4)
fused_node_kernel(const float* __restrict__ w_u2,
                  const float* __restrict__ b_u1,
                  const float* __restrict__ b_u2,
                  float* __restrict__ out) {
    __shared__ float As[128 * 66];
    const int row0 = blockIdx.x * 128;
    const int tid = threadIdx.x;
    const int tc = tid & 15, tr = tid >> 4;
    const int j0 = tc * 4, r0 = tr * 8;

    for (int idx = tid; idx < 128 * 64; idx += 256) {
        int r = idx >> 6, k = idx & 63;
        int row = row0 + r;
        As[r * 66 + k] = (row < NN) ? g_hsum[(size_t)row * 64 + k] : 0.f;
    }
    __syncthreads();

    float4 acc[8];
    #pragma unroll
    for (int i = 0; i < 8; i++) acc[i] = make_float4(0.f, 0.f, 0.f, 0.f);
    #pragma unroll 8
    for (int k = 0; k < 64; k++) {
        float4 w = *reinterpret_cast<const float4*>(&g_Wc[k * 64 + j0]);
        #pragma unroll
        for (int i = 0; i < 8; i++) {
            float a = As[(r0 + i) * 66 + k];
            acc[i].x += a * w.x; acc[i].y += a * w.y;
            acc[i].z += a * w.z; acc[i].w += a * w.w;
        }
    }
    __syncthreads();

    {
        float4 bc = *reinterpret_cast<const float4*>(&g_bc[j0]);
        float4 bu = *reinterpret_cast<const float4*>(&b_u1[j0]);
        #pragma unroll
        for (int i = 0; i < 8; i++) {
            int r = r0 + i;
            int row = row0 + r;
            if (row < NN) {
                float4 xu = *reinterpret_cast<const float4*>(
                    &g_xu[(size_t)row * 64 + j0]);
                float dg = (float)g_deg[row];
                As[r * 66 + j0 + 0] = fmaxf(acc[i].x + xu.x + dg * bc.x + bu.x, 0.f);
                As[r * 66 + j0 + 1] = fmaxf(acc[i].y + xu.y + dg * bc.y + bu.y, 0.f);
                As[r * 66 + j0 + 2] = fmaxf(acc[i].z + xu.z + dg * bc.z + bu.z, 0.f);
                As[r * 66 + j0 + 3] = fmaxf(acc[i].w + xu.w + dg * bc.w + bu.w, 0.f);
            } else {
                As[r * 66 + j0 + 0] = 0.f;
                As[r * 66 + j0 + 1] = 0.f;
                As[r * 66 + j0 + 2] = 0.f;
                As[r * 66 + j0 + 3] = 0.f;
            }
        }
    }
    __syncthreads();

    #pragma unroll
    for (int i = 0; i < 8; i++) acc[i] = make_float4(0.f, 0.f, 0.f, 0.f);
    #pragma unroll 8
    for (int k = 0; k < 64; k++) {
        float4 w = *reinterpret_cast<const float4*>(&w_u2[k * 64 + j0]);
        #pragma unroll
        for (int i = 0; i < 8; i++) {
            float a = As[(r0 + i) * 66 + k];
            acc[i].x += a * w.x; acc[i].y += a * w.y;
            acc[i].z += a * w.z; acc[i].w += a * w.w;
        }
    }

    float4 b2 = *reinterpret_cast<const float4*>(&b_u2[j0]);
    #pragma unroll
    for (int i = 0; i < 8; i++) {
        int row = row0 + r0 + i;
        if (row < NN) {
            float4 v;
            v.x = acc[i].x + b2.x; v.y = acc[i].y + b2.y;
            v.z = acc[i].z + b2.z; v.w = acc[i].w + b2.w;
            *reinterpret_cast<float4*>(&out[(size_t)row * 64 + j0]) = v;
        }
    }
}

// ---------------------------------------------------------------------------
// Launch
// ---------------------------------------------------------------------------
extern "C" void kernel_launch(void* const* d_in, const int* in_sizes, int n_in,
                              void* d_out, int out_size) {
    const float* node_f = (const float*)d_in[0];
    const float* edge_f = (const float*)d_in[1];
    const int*   eidx   = (const int*)d_in[2];
    const float* w_m1   = (const float*)d_in[3];
    const float* b_m1   = (const float*)d_in[4];
    const float* w_m2   = (const float*)d_in[5];
    const float* b_m2   = (const float*)d_in[6];
    const float* w_u1   = (const float*)d_in[7];
    const float* b_u1   = (const float*)d_in[8];
    const float* w_u2   = (const float*)d_in[9];
    const float* b_u2   = (const float*)d_in[10];
    float* out = (float*)d_out;

    const int edgeBlocks = (NE + 63) / 64;     // 19532

    mega_pre_kernel<<<PGB + ZB + 65, 256>>>(node_f, w_m1, w_u1, w_m2, b_m2);
    edge_kernel<<<edgeBlocks, 256>>>(edge_f, eidx, w_m1, b_m1);
    fused_node_kernel<<<PGB, 256>>>(w_u2, b_u1, b_u2, out);
}

// round 10
// speedup vs baseline: 1.1941x; 1.1159x over previous
#include <cuda_runtime.h>
#include <cuda_fp16.h>
#include <cstdint>

#define NN 50000      // nodes
#define NE 1250000    // edges
#define DN 64         // node feat
#define DE 16         // edge feat
#define DH 64         // hidden

// ---------------------------------------------------------------------------
// Scratch (device globals; no allocation allowed)
// ---------------------------------------------------------------------------
__device__ float   g_srcpart[NN * DH];  // node_features @ W_m1[0:64]
__device__ float   g_xu[NN * DH];       // node_features @ W_u1[0:64]
__device__ __half2 g_hsum2[NN * 32];    // segment-sum of relu hidden (f16x2)
__device__ int     g_deg[NN];           // in-degree per node
__device__ float   g_Wc[DH * DH];       // W_m2 @ W_u1[64:128]
__device__ float   g_bc[DH];            // b_m2 @ W_u1[64:128]

// ---------------------------------------------------------------------------
// init: blocks [0,ZB2) zero g_hsum2 (+ g_deg).  blocks ZB2+k (k<64): Wc row k.
//       block ZB2+64: bc.
// ---------------------------------------------------------------------------
#define ZB2 1563   // ceil(NN*32*4 bytes / 16 / 256) = ceil(400000/256)
__global__ void init_kernel(const float* __restrict__ w_m2,
                            const float* __restrict__ b_m2,
                            const float* __restrict__ w_u1) {
    const int tid = threadIdx.x;
    if (blockIdx.x < ZB2) {
        int idx = blockIdx.x * 256 + tid;
        if (idx < NN * 8)   // NN*32 half2 = NN*8 float4
            reinterpret_cast<float4*>(g_hsum2)[idx] = make_float4(0.f, 0.f, 0.f, 0.f);
        if (idx < NN) g_deg[idx] = 0;
    } else if (blockIdx.x < ZB2 + 64) {
        int k = blockIdx.x - ZB2;
        if (tid < DH) {
            float s = 0.f;
            #pragma unroll 8
            for (int m = 0; m < DH; m++)
                s += w_m2[k * DH + m] * w_u1[(DN + m) * DH + tid];
            g_Wc[k * DH + tid] = s;
        }
    } else {
        if (tid < DH) {
            float s = 0.f;
            #pragma unroll 8
            for (int m = 0; m < DH; m++)
                s += b_m2[m] * w_u1[(DN + m) * DH + tid];
            g_bc[tid] = s;
        }
    }
}

// ---------------------------------------------------------------------------
// pre_gemm: stage X tile (128x64) once, produce BOTH
//   g_srcpart = X @ w_m1[0:64]   and   g_xu = X @ w_u1[0:64].
// ---------------------------------------------------------------------------
#define PGB 391    // ceil(NN/128)
__global__ void pre_gemm_kernel(const float* __restrict__ X,
                                const float* __restrict__ w_m1,
                                const float* __restrict__ w_u1) {
    __shared__ float As[128 * 66];
    const int row0 = blockIdx.x * 128;
    const int tid = threadIdx.x;

    for (int idx = tid; idx < 128 * 64; idx += 256) {
        int r = idx >> 6, k = idx & 63;
        int row = row0 + r;
        As[r * 66 + k] = (row < NN) ? X[(size_t)row * 64 + k] : 0.f;
    }
    __syncthreads();

    const int tc = tid & 15, tr = tid >> 4;
    const int j0 = tc * 4, r0 = tr * 8;
    float4 acc[8];

    #pragma unroll
    for (int i = 0; i < 8; i++) acc[i] = make_float4(0.f, 0.f, 0.f, 0.f);
    #pragma unroll 8
    for (int k = 0; k < 64; k++) {
        float4 w = *reinterpret_cast<const float4*>(&w_m1[k * 64 + j0]);
        #pragma unroll
        for (int i = 0; i < 8; i++) {
            float a = As[(r0 + i) * 66 + k];
            acc[i].x += a * w.x; acc[i].y += a * w.y;
            acc[i].z += a * w.z; acc[i].w += a * w.w;
        }
    }
    #pragma unroll
    for (int i = 0; i < 8; i++) {
        int row = row0 + r0 + i;
        if (row < NN)
            *reinterpret_cast<float4*>(&g_srcpart[(size_t)row * 64 + j0]) = acc[i];
    }

    #pragma unroll
    for (int i = 0; i < 8; i++) acc[i] = make_float4(0.f, 0.f, 0.f, 0.f);
    #pragma unroll 8
    for (int k = 0; k < 64; k++) {
        float4 w = *reinterpret_cast<const float4*>(&w_u1[k * 64 + j0]);
        #pragma unroll
        for (int i = 0; i < 8; i++) {
            float a = As[(r0 + i) * 66 + k];
            acc[i].x += a * w.x; acc[i].y += a * w.y;
            acc[i].z += a * w.z; acc[i].w += a * w.w;
        }
    }
    #pragma unroll
    for (int i = 0; i < 8; i++) {
        int row = row0 + r0 + i;
        if (row < NN)
            *reinterpret_cast<float4*>(&g_xu[(size_t)row * 64 + j0]) = acc[i];
    }
}

// ---------------------------------------------------------------------------
// Edge kernel v4: 64 edges / 256-thread block; 2 edges x 8 cols per thread.
// One red.global.add.v4.f16x2 per (thread, edge) -> 10M REDG total (halved).
// ---------------------------------------------------------------------------
__global__ void __launch_bounds__(256, 4)
edge_kernel(const float* __restrict__ ef,
            const int* __restrict__ eidx,
            const float* __restrict__ w_m1,
            const float* __restrict__ b_m1) {
    __shared__ float Es[64 * 17];
    __shared__ int s_sh[64];
    __shared__ int d_sh[64];
    const int e0 = blockIdx.x * 64;
    const int tid = threadIdx.x;

    if (tid < 64) {
        int e = e0 + tid;
        int s = 0, d = 0;
        if (e < NE) {
            s = eidx[e];
            d = eidx[NE + e];
            atomicAdd(&g_deg[d], 1);
        }
        s_sh[tid] = s;
        d_sh[tid] = d;
    }
    {
        int r = tid >> 2, q = tid & 3;   // 64 edges x 4 float4 = 256 loads
        int e = e0 + r;
        float4 v = make_float4(0.f, 0.f, 0.f, 0.f);
        if (e < NE)
            v = reinterpret_cast<const float4*>(ef)[(size_t)e * 4 + q];
        Es[r * 17 + q * 4 + 0] = v.x;
        Es[r * 17 + q * 4 + 1] = v.y;
        Es[r * 17 + q * 4 + 2] = v.z;
        Es[r * 17 + q * 4 + 3] = v.w;
    }
    __syncthreads();

    const int tc = tid & 7, tr = tid >> 3;   // 8 col-groups x 32 row-groups
    const int j0 = tc * 8, r0 = tr * 2;

    // Prefetch srcpart gathers (2 edges x 2 float4, independent L2 hits).
    float4 spA[2], spB[2];
    #pragma unroll
    for (int i = 0; i < 2; i++) {
        int e = e0 + r0 + i;
        const float* p = &g_srcpart[(size_t)s_sh[r0 + i] * 64 + j0];
        if (e < NE) {
            spA[i] = *reinterpret_cast<const float4*>(p);
            spB[i] = *reinterpret_cast<const float4*>(p + 4);
        } else {
            spA[i] = make_float4(0.f, 0.f, 0.f, 0.f);
            spB[i] = make_float4(0.f, 0.f, 0.f, 0.f);
        }
    }

    float4 accA[2], accB[2];
    #pragma unroll
    for (int i = 0; i < 2; i++) {
        accA[i] = make_float4(0.f, 0.f, 0.f, 0.f);
        accB[i] = make_float4(0.f, 0.f, 0.f, 0.f);
    }

    #pragma unroll
    for (int k = 0; k < 16; k++) {
        float4 wA = *reinterpret_cast<const float4*>(&w_m1[(DN + k) * 64 + j0]);
        float4 wB = *reinterpret_cast<const float4*>(&w_m1[(DN + k) * 64 + j0 + 4]);
        #pragma unroll
        for (int i = 0; i < 2; i++) {
            float a = Es[(r0 + i) * 17 + k];
            accA[i].x += a * wA.x; accA[i].y += a * wA.y;
            accA[i].z += a * wA.z; accA[i].w += a * wA.w;
            accB[i].x += a * wB.x; accB[i].y += a * wB.y;
            accB[i].z += a * wB.z; accB[i].w += a * wB.w;
        }
    }

    float4 bA = *reinterpret_cast<const float4*>(&b_m1[j0]);
    float4 bB = *reinterpret_cast<const float4*>(&b_m1[j0 + 4]);

    #pragma unroll
    for (int i = 0; i < 2; i++) {
        int e = e0 + r0 + i;
        if (e < NE) {
            float h0 = fmaxf(accA[i].x + spA[i].x + bA.x, 0.f);
            float h1 = fmaxf(accA[i].y + spA[i].y + bA.y, 0.f);
            float h2 = fmaxf(accA[i].z + spA[i].z + bA.z, 0.f);
            float h3 = fmaxf(accA[i].w + spA[i].w + bA.w, 0.f);
            float h4 = fmaxf(accB[i].x + spB[i].x + bB.x, 0.f);
            float h5 = fmaxf(accB[i].y + spB[i].y + bB.y, 0.f);
            float h6 = fmaxf(accB[i].z + spB[i].z + bB.z, 0.f);
            float h7 = fmaxf(accB[i].w + spB[i].w + bB.w, 0.f);
            __half2 q0 = __floats2half2_rn(h0, h1);
            __half2 q1 = __floats2half2_rn(h2, h3);
            __half2 q2 = __floats2half2_rn(h4, h5);
            __half2 q3 = __floats2half2_rn(h6, h7);
            uint32_t u0 = *reinterpret_cast<uint32_t*>(&q0);
            uint32_t u1 = *reinterpret_cast<uint32_t*>(&q1);
            uint32_t u2 = *reinterpret_cast<uint32_t*>(&q2);
            uint32_t u3 = *reinterpret_cast<uint32_t*>(&q3);
            __half2* p = &g_hsum2[(size_t)d_sh[r0 + i] * 32 + (j0 >> 1)];
            asm volatile("red.global.add.noftz.v4.f16x2 [%0], {%1, %2, %3, %4};"
                         :: "l"(p), "r"(u0), "r"(u1), "r"(u2), "r"(u3)
                         : "memory");
        }
    }
}

// ---------------------------------------------------------------------------
// Fused node update (R7 config, regs free): 128-row tiles, 8x4/thread.
//   T = relu(Hsum@Wc + xu + deg*bc + b_u1);  out = T @ w_u2 + b_u2
// Hsum staged from f16x2 with conversion.
// ---------------------------------------------------------------------------
__global__ void fused_node_kernel(const float* __restrict__ w_u2,
                                  const float* __restrict__ b_u1,
                                  const float* __restrict__ b_u2,
                                  float* __restrict__ out) {
    __shared__ float As[128 * 66];
    const int row0 = blockIdx.x * 128;
    const int tid = threadIdx.x;
    const int tc = tid & 15, tr = tid >> 4;
    const int j0 = tc * 4, r0 = tr * 8;

    // stage Hsum tile (convert f16 -> f32): 128 rows x 8 groups of 8 cols
    for (int idx = tid; idx < 128 * 8; idx += 256) {
        int r = idx >> 3, g = idx & 7;
        int row = row0 + r;
        float* dst = &As[r * 66 + g * 8];
        if (row < NN) {
            uint4 v = reinterpret_cast<const uint4*>(g_hsum2)[(size_t)row * 8 + g];
            __half2 q0 = *reinterpret_cast<__half2*>(&v.x);
            __half2 q1 = *reinterpret_cast<__half2*>(&v.y);
            __half2 q2 = *reinterpret_cast<__half2*>(&v.z);
            __half2 q3 = *reinterpret_cast<__half2*>(&v.w);
            float2 f0 = __half22float2(q0);
            float2 f1 = __half22float2(q1);
            float2 f2 = __half22float2(q2);
            float2 f3 = __half22float2(q3);
            dst[0] = f0.x; dst[1] = f0.y; dst[2] = f1.x; dst[3] = f1.y;
            dst[4] = f2.x; dst[5] = f2.y; dst[6] = f3.x; dst[7] = f3.y;
        } else {
            #pragma unroll
            for (int t = 0; t < 8; t++) dst[t] = 0.f;
        }
    }
    __syncthreads();

    float4 acc[8];
    #pragma unroll
    for (int i = 0; i < 8; i++) acc[i] = make_float4(0.f, 0.f, 0.f, 0.f);
    #pragma unroll 8
    for (int k = 0; k < 64; k++) {
        float4 w = *reinterpret_cast<const float4*>(&g_Wc[k * 64 + j0]);
        #pragma unroll
        for (int i = 0; i < 8; i++) {
            float a = As[(r0 + i) * 66 + k];
            acc[i].x += a * w.x; acc[i].y += a * w.y;
            acc[i].z += a * w.z; acc[i].w += a * w.w;
        }
    }
    __syncthreads();

    {
        float4 bc = *reinterpret_cast<const float4*>(&g_bc[j0]);
        float4 bu = *reinterpret_cast<const float4*>(&b_u1[j0]);
        #pragma unroll
        for (int i = 0; i < 8; i++) {
            int r = r0 + i;
            int row = row0 + r;
            if (row < NN) {
                float4 xu = *reinterpret_cast<const float4*>(
                    &g_xu[(size_t)row * 64 + j0]);
                float dg = (float)g_deg[row];
                As[r * 66 + j0 + 0] = fmaxf(acc[i].x + xu.x + dg * bc.x + bu.x, 0.f);
                As[r * 66 + j0 + 1] = fmaxf(acc[i].y + xu.y + dg * bc.y + bu.y, 0.f);
                As[r * 66 + j0 + 2] = fmaxf(acc[i].z + xu.z + dg * bc.z + bu.z, 0.f);
                As[r * 66 + j0 + 3] = fmaxf(acc[i].w + xu.w + dg * bc.w + bu.w, 0.f);
            } else {
                As[r * 66 + j0 + 0] = 0.f;
                As[r * 66 + j0 + 1] = 0.f;
                As[r * 66 + j0 + 2] = 0.f;
                As[r * 66 + j0 + 3] = 0.f;
            }
        }
    }
    __syncthreads();

    #pragma unroll
    for (int i = 0; i < 8; i++) acc[i] = make_float4(0.f, 0.f, 0.f, 0.f);
    #pragma unroll 8
    for (int k = 0; k < 64; k++) {
        float4 w = *reinterpret_cast<const float4*>(&w_u2[k * 64 + j0]);
        #pragma unroll
        for (int i = 0; i < 8; i++) {
            float a = As[(r0 + i) * 66 + k];
            acc[i].x += a * w.x; acc[i].y += a * w.y;
            acc[i].z += a * w.z; acc[i].w += a * w.w;
        }
    }

    float4 b2 = *reinterpret_cast<const float4*>(&b_u2[j0]);
    #pragma unroll
    for (int i = 0; i < 8; i++) {
        int row = row0 + r0 + i;
        if (row < NN) {
            float4 v;
            v.x = acc[i].x + b2.x; v.y = acc[i].y + b2.y;
            v.z = acc[i].z + b2.z; v.w = acc[i].w + b2.w;
            *reinterpret_cast<float4*>(&out[(size_t)row * 64 + j0]) = v;
        }
    }
}

// ---------------------------------------------------------------------------
// Launch
// ---------------------------------------------------------------------------
extern "C" void kernel_launch(void* const* d_in, const int* in_sizes, int n_in,
                              void* d_out, int out_size) {
    const float* node_f = (const float*)d_in[0];
    const float* edge_f = (const float*)d_in[1];
    const int*   eidx   = (const int*)d_in[2];
    const float* w_m1   = (const float*)d_in[3];
    const float* b_m1   = (const float*)d_in[4];
    const float* w_m2   = (const float*)d_in[5];
    const float* b_m2   = (const float*)d_in[6];
    const float* w_u1   = (const float*)d_in[7];
    const float* b_u1   = (const float*)d_in[8];
    const float* w_u2   = (const float*)d_in[9];
    const float* b_u2   = (const float*)d_in[10];
    float* out = (float*)d_out;

    const int edgeBlocks = (NE + 63) / 64;     // 19532

    init_kernel<<<ZB2 + 65, 256>>>(w_m2, b_m2, w_u1);
    pre_gemm_kernel<<<PGB, 256>>>(node_f, w_m1, w_u1);
    edge_kernel<<<edgeBlocks, 256>>>(edge_f, eidx, w_m1, b_m1);
    fused_node_kernel<<<PGB, 256>>>(w_u2, b_u1, b_u2, out);
}

// round 11
// speedup vs baseline: 1.6436x; 1.3764x over previous
#include <cuda_runtime.h>
#include <cstdint>

#define NN 50000      // nodes
#define NE 1250000    // edges
#define DN 64         // node feat
#define DE 16         // edge feat
#define DH 64         // hidden

// ---------------------------------------------------------------------------
// Scratch (device globals; no allocation allowed)
// ---------------------------------------------------------------------------
__device__ float g_srcpart[NN * DH];   // node_features @ W_m1[0:64]
__device__ float g_xu[NN * DH];        // node_features @ W_u1[0:64]
__device__ float g_hsum[NN * DH];      // segment-sum of relu hidden
__device__ int   g_deg[NN];            // in-degree per node
__device__ float g_Wc[DH * DH];        // W_m2 @ W_u1[64:128]
__device__ float g_bc[DH];             // b_m2 @ W_u1[64:128]

// ---------------------------------------------------------------------------
// init: blocks [0,ZB) zero g_hsum/g_deg.
//       blocks ZB+k (k<64): Wc row k (coalesced over tid).  block ZB+64: bc.
// ---------------------------------------------------------------------------
#define ZB 3125   // NN*DH/4 / 256
__global__ void init_kernel(const float* __restrict__ w_m2,
                            const float* __restrict__ b_m2,
                            const float* __restrict__ w_u1) {
    const int tid = threadIdx.x;
    if (blockIdx.x < ZB) {
        int idx = blockIdx.x * 256 + tid;
        reinterpret_cast<float4*>(g_hsum)[idx] = make_float4(0.f, 0.f, 0.f, 0.f);
        if (idx < NN) g_deg[idx] = 0;
    } else if (blockIdx.x < ZB + 64) {
        int k = blockIdx.x - ZB;
        if (tid < DH) {
            float s = 0.f;
            #pragma unroll 8
            for (int m = 0; m < DH; m++)
                s += w_m2[k * DH + m] * w_u1[(DN + m) * DH + tid];
            g_Wc[k * DH + tid] = s;
        }
    } else {
        if (tid < DH) {
            float s = 0.f;
            #pragma unroll 8
            for (int m = 0; m < DH; m++)
                s += b_m2[m] * w_u1[(DN + m) * DH + tid];
            g_bc[tid] = s;
        }
    }
}

// ---------------------------------------------------------------------------
// pre_gemm: blocks [0, PGB): stage X tile once -> g_srcpart = X@Wm1a and
//           g_xu = X@Wu1a (128-row tiles, 8x4/thread).
//           blocks [PGB, PGB+DEGB): deg histogram, 8 edges per thread
//           (coalesced dst reads; int atomics overlap the GEMM blocks).
// ---------------------------------------------------------------------------
#define PGB 391    // ceil(NN/128)
#define DEGB 611   // ceil(NE / (256*8))
__global__ void pre_gemm_kernel(const float* __restrict__ X,
                                const float* __restrict__ w_m1,
                                const float* __restrict__ w_u1,
                                const int* __restrict__ eidx) {
    const int tid = threadIdx.x;

    if (blockIdx.x >= PGB) {
        int base = (blockIdx.x - PGB) * 2048 + tid;
        #pragma unroll
        for (int i = 0; i < 8; i++) {
            int e = base + i * 256;
            if (e < NE) atomicAdd(&g_deg[eidx[NE + e]], 1);
        }
        return;
    }

    __shared__ float As[128 * 66];
    const int row0 = blockIdx.x * 128;

    for (int idx = tid; idx < 128 * 64; idx += 256) {
        int r = idx >> 6, k = idx & 63;
        int row = row0 + r;
        As[r * 66 + k] = (row < NN) ? X[(size_t)row * 64 + k] : 0.f;
    }
    __syncthreads();

    const int tc = tid & 15, tr = tid >> 4;
    const int j0 = tc * 4, r0 = tr * 8;
    float4 acc[8];

    // --- srcpart = X @ w_m1[0:64] ---
    #pragma unroll
    for (int i = 0; i < 8; i++) acc[i] = make_float4(0.f, 0.f, 0.f, 0.f);
    #pragma unroll 8
    for (int k = 0; k < 64; k++) {
        float4 w = *reinterpret_cast<const float4*>(&w_m1[k * 64 + j0]);
        #pragma unroll
        for (int i = 0; i < 8; i++) {
            float a = As[(r0 + i) * 66 + k];
            acc[i].x += a * w.x; acc[i].y += a * w.y;
            acc[i].z += a * w.z; acc[i].w += a * w.w;
        }
    }
    #pragma unroll
    for (int i = 0; i < 8; i++) {
        int row = row0 + r0 + i;
        if (row < NN)
            *reinterpret_cast<float4*>(&g_srcpart[(size_t)row * 64 + j0]) = acc[i];
    }

    // --- xu = X @ w_u1[0:64] ---
    #pragma unroll
    for (int i = 0; i < 8; i++) acc[i] = make_float4(0.f, 0.f, 0.f, 0.f);
    #pragma unroll 8
    for (int k = 0; k < 64; k++) {
        float4 w = *reinterpret_cast<const float4*>(&w_u1[k * 64 + j0]);
        #pragma unroll
        for (int i = 0; i < 8; i++) {
            float a = As[(r0 + i) * 66 + k];
            acc[i].x += a * w.x; acc[i].y += a * w.y;
            acc[i].z += a * w.z; acc[i].w += a * w.w;
        }
    }
    #pragma unroll
    for (int i = 0; i < 8; i++) {
        int row = row0 + r0 + i;
        if (row < NN)
            *reinterpret_cast<float4*>(&g_xu[(size_t)row * 64 + j0]) = acc[i];
    }
}

// ---------------------------------------------------------------------------
// Edge kernel (R7 config, deg atomic removed): 64 edges / 256-thread block,
// 4 edges x 4 cols per thread, 4 blocks/SM.
// ---------------------------------------------------------------------------
__global__ void __launch_bounds__(256, 4)
edge_kernel(const float* __restrict__ ef,
            const int* __restrict__ eidx,
            const float* __restrict__ w_m1,
            const float* __restrict__ b_m1) {
    __shared__ float Es[64 * 17];
    __shared__ int s_sh[64];
    __shared__ int d_sh[64];
    const int e0 = blockIdx.x * 64;
    const int tid = threadIdx.x;

    if (tid < 64) {
        int e = e0 + tid;
        int s = 0, d = 0;
        if (e < NE) {
            s = eidx[e];
            d = eidx[NE + e];
        }
        s_sh[tid] = s;
        d_sh[tid] = d;
    }
    {
        int r = tid >> 2, q = tid & 3;   // 64 edges x 4 float4 = 256 loads
        int e = e0 + r;
        float4 v = make_float4(0.f, 0.f, 0.f, 0.f);
        if (e < NE)
            v = reinterpret_cast<const float4*>(ef)[(size_t)e * 4 + q];
        Es[r * 17 + q * 4 + 0] = v.x;
        Es[r * 17 + q * 4 + 1] = v.y;
        Es[r * 17 + q * 4 + 2] = v.z;
        Es[r * 17 + q * 4 + 3] = v.w;
    }
    __syncthreads();

    const int tc = tid & 15, tr = tid >> 4;
    const int j0 = tc * 4, r0 = tr * 4;

    // Prefetch the 4 srcpart gathers early (independent L2 hits, MLP=4).
    float4 sp[4];
    #pragma unroll
    for (int i = 0; i < 4; i++) {
        int e = e0 + r0 + i;
        const float* p = &g_srcpart[(size_t)s_sh[r0 + i] * 64 + j0];
        sp[i] = (e < NE) ? *reinterpret_cast<const float4*>(p)
                         : make_float4(0.f, 0.f, 0.f, 0.f);
    }

    float4 acc[4];
    #pragma unroll
    for (int i = 0; i < 4; i++) acc[i] = make_float4(0.f, 0.f, 0.f, 0.f);

    #pragma unroll
    for (int k = 0; k < 16; k++) {
        float4 w = *reinterpret_cast<const float4*>(&w_m1[(DN + k) * 64 + j0]);
        #pragma unroll
        for (int i = 0; i < 4; i++) {
            float a = Es[(r0 + i) * 17 + k];
            acc[i].x += a * w.x; acc[i].y += a * w.y;
            acc[i].z += a * w.z; acc[i].w += a * w.w;
        }
    }

    float4 b = *reinterpret_cast<const float4*>(&b_m1[j0]);

    #pragma unroll
    for (int i = 0; i < 4; i++) {
        int e = e0 + r0 + i;
        if (e < NE) {
            float hx = fmaxf(acc[i].x + sp[i].x + b.x, 0.f);
            float hy = fmaxf(acc[i].y + sp[i].y + b.y, 0.f);
            float hz = fmaxf(acc[i].z + sp[i].z + b.z, 0.f);
            float hw = fmaxf(acc[i].w + sp[i].w + b.w, 0.f);
            float* p = &g_hsum[(size_t)d_sh[r0 + i] * 64 + j0];
            asm volatile("red.global.add.v4.f32 [%0], {%1, %2, %3, %4};"
                         :: "l"(p), "f"(hx), "f"(hy), "f"(hz), "f"(hw)
                         : "memory");
        }
    }
}

// ---------------------------------------------------------------------------
// Fused node update (R7 config, unchanged): 128-row tiles, 8x4/thread.
//   T = relu(Hsum@Wc + xu + deg*bc + b_u1);  out = T @ w_u2 + b_u2
// ---------------------------------------------------------------------------
__global__ void fused_node_kernel(const float* __restrict__ w_u2,
                                  const float* __restrict__ b_u1,
                                  const float* __restrict__ b_u2,
                                  float* __restrict__ out) {
    __shared__ float As[128 * 66];
    const int row0 = blockIdx.x * 128;
    const int tid = threadIdx.x;
    const int tc = tid & 15, tr = tid >> 4;
    const int j0 = tc * 4, r0 = tr * 8;

    for (int idx = tid; idx < 128 * 64; idx += 256) {
        int r = idx >> 6, k = idx & 63;
        int row = row0 + r;
        As[r * 66 + k] = (row < NN) ? g_hsum[(size_t)row * 64 + k] : 0.f;
    }
    __syncthreads();

    float4 acc[8];
    #pragma unroll
    for (int i = 0; i < 8; i++) acc[i] = make_float4(0.f, 0.f, 0.f, 0.f);
    #pragma unroll 8
    for (int k = 0; k < 64; k++) {
        float4 w = *reinterpret_cast<const float4*>(&g_Wc[k * 64 + j0]);
        #pragma unroll
        for (int i = 0; i < 8; i++) {
            float a = As[(r0 + i) * 66 + k];
            acc[i].x += a * w.x; acc[i].y += a * w.y;
            acc[i].z += a * w.z; acc[i].w += a * w.w;
        }
    }
    __syncthreads();

    {
        float4 bc = *reinterpret_cast<const float4*>(&g_bc[j0]);
        float4 bu = *reinterpret_cast<const float4*>(&b_u1[j0]);
        #pragma unroll
        for (int i = 0; i < 8; i++) {
            int r = r0 + i;
            int row = row0 + r;
            if (row < NN) {
                float4 xu = *reinterpret_cast<const float4*>(
                    &g_xu[(size_t)row * 64 + j0]);
                float dg = (float)g_deg[row];
                As[r * 66 + j0 + 0] = fmaxf(acc[i].x + xu.x + dg * bc.x + bu.x, 0.f);
                As[r * 66 + j0 + 1] = fmaxf(acc[i].y + xu.y + dg * bc.y + bu.y, 0.f);
                As[r * 66 + j0 + 2] = fmaxf(acc[i].z + xu.z + dg * bc.z + bu.z, 0.f);
                As[r * 66 + j0 + 3] = fmaxf(acc[i].w + xu.w + dg * bc.w + bu.w, 0.f);
            } else {
                As[r * 66 + j0 + 0] = 0.f;
                As[r * 66 + j0 + 1] = 0.f;
                As[r * 66 + j0 + 2] = 0.f;
                As[r * 66 + j0 + 3] = 0.f;
            }
        }
    }
    __syncthreads();

    #pragma unroll
    for (int i = 0; i < 8; i++) acc[i] = make_float4(0.f, 0.f, 0.f, 0.f);
    #pragma unroll 8
    for (int k = 0; k < 64; k++) {
        float4 w = *reinterpret_cast<const float4*>(&w_u2[k * 64 + j0]);
        #pragma unroll
        for (int i = 0; i < 8; i++) {
            float a = As[(r0 + i) * 66 + k];
            acc[i].x += a * w.x; acc[i].y += a * w.y;
            acc[i].z += a * w.z; acc[i].w += a * w.w;
        }
    }

    float4 b2 = *reinterpret_cast<const float4*>(&b_u2[j0]);
    #pragma unroll
    for (int i = 0; i < 8; i++) {
        int row = row0 + r0 + i;
        if (row < NN) {
            float4 v;
            v.x = acc[i].x + b2.x; v.y = acc[i].y + b2.y;
            v.z = acc[i].z + b2.z; v.w = acc[i].w + b2.w;
            *reinterpret_cast<float4*>(&out[(size_t)row * 64 + j0]) = v;
        }
    }
}

// ---------------------------------------------------------------------------
// Launch
// ---------------------------------------------------------------------------
extern "C" void kernel_launch(void* const* d_in, const int* in_sizes, int n_in,
                              void* d_out, int out_size) {
    const float* node_f = (const float*)d_in[0];
    const float* edge_f = (const float*)d_in[1];
    const int*   eidx   = (const int*)d_in[2];
    const float* w_m1   = (const float*)d_in[3];
    const float* b_m1   = (const float*)d_in[4];
    const float* w_m2   = (const float*)d_in[5];
    const float* b_m2   = (const float*)d_in[6];
    const float* w_u1   = (const float*)d_in[7];
    const float* b_u1   = (const float*)d_in[8];
    const float* w_u2   = (const float*)d_in[9];
    const float* b_u2   = (const float*)d_in[10];
    float* out = (float*)d_out;

    const int edgeBlocks = (NE + 63) / 64;     // 19532

    init_kernel<<<ZB + 65, 256>>>(w_m2, b_m2, w_u1);
    pre_gemm_kernel<<<PGB + DEGB, 256>>>(node_f, w_m1, w_u1, eidx);
    edge_kernel<<<edgeBlocks, 256>>>(edge_f, eidx, w_m1, b_m1);
    fused_node_kernel<<<PGB, 256>>>(w_u2, b_u1, b_u2, out);
}